// round 14
// baseline (speedup 1.0000x reference)
#include <cuda_runtime.h>
#include <cuda_fp16.h>

#define N_NODES 100000
#define DIM_IN 128
#define DIM_OUT 64
#define N_EDGES 1600000
#define PAD 128   // combined 3-axis bucket per row; Poisson(48) => overflow ~impossible

// Scratch (device globals — no runtime allocation allowed)
__device__ __half g_support[(size_t)3 * N_NODES * DIM_OUT];           // 38.4 MB (fp16)
__device__ int g_cnt[N_NODES];                                        // 0.4 MB
__device__ long long g_bucket[(size_t)N_NODES * PAD];                 // 102.4 MB

// ---------------- tf32 helpers ----------------------------------------------
__device__ __forceinline__ unsigned f2tf32(float f) {
    unsigned r;
    asm("cvt.rna.tf32.f32 %0, %1;" : "=r"(r) : "f"(f));
    return r;
}

__device__ __forceinline__ void mma_tf32(float (&c)[4], const unsigned (&a)[4],
                                         const unsigned (&b)[2]) {
    asm volatile(
        "mma.sync.aligned.m16n8k8.row.col.f32.tf32.tf32.f32 "
        "{%0,%1,%2,%3}, {%4,%5,%6,%7}, {%8,%9}, {%0,%1,%2,%3};"
        : "+f"(c[0]), "+f"(c[1]), "+f"(c[2]), "+f"(c[3])
        : "r"(a[0]), "r"(a[1]), "r"(a[2]), "r"(a[3]), "r"(b[0]), "r"(b[1]));
}

// ---------------- GEMM: support[ax] = x @ w[ax] (fp16 out), ax per block.y ---
#define XS_STRIDE 36
#define WS_STRIDE 72
__global__ __launch_bounds__(256) void gemm_tf32_kernel(const float* __restrict__ x,
                                                        const float* __restrict__ w) {
    __shared__ unsigned ws[32 * WS_STRIDE];       // 9.2 KB  (32-row W chunk)
    __shared__ unsigned xs[128 * XS_STRIDE];      // 18.4 KB (32-col X chunk)
    const int axis = blockIdx.y;
    const int rowBase = blockIdx.x * 128;
    const int t = threadIdx.x;
    const int lane = t & 31, warp = t >> 5;

    float acc[8][4];
#pragma unroll
    for (int nt = 0; nt < 8; nt++)
#pragma unroll
        for (int i = 0; i < 4; i++) acc[nt][i] = 0.f;

    const float4* w4 = (const float4*)(w + (size_t)axis * DIM_IN * DIM_OUT);

    for (int k0 = 0; k0 < DIM_IN; k0 += 32) {
#pragma unroll
        for (int i = 0; i < 2; i++) {
            int idx = t + i * 256;
            int k = idx >> 4, n4 = idx & 15;
            float4 v = __ldg(w4 + (k0 + k) * 16 + n4);
            uint4 u = make_uint4(f2tf32(v.x), f2tf32(v.y), f2tf32(v.z), f2tf32(v.w));
            *(uint4*)&ws[k * WS_STRIDE + n4 * 4] = u;
        }
#pragma unroll
        for (int i = 0; i < 4; i++) {
            int f = t + i * 256;
            int r = f >> 3, c4 = f & 7;
            int gr = rowBase + r;
            float4 v = make_float4(0.f, 0.f, 0.f, 0.f);
            if (gr < N_NODES) v = *(const float4*)(x + (size_t)gr * DIM_IN + k0 + c4 * 4);
            uint4 u = make_uint4(f2tf32(v.x), f2tf32(v.y), f2tf32(v.z), f2tf32(v.w));
            *(uint4*)&xs[r * XS_STRIDE + c4 * 4] = u;
        }
        __syncthreads();

#pragma unroll
        for (int kk = 0; kk < 32; kk += 8) {
            unsigned a[4];
            int ar = warp * 16 + (lane >> 2);
            int ac = kk + (lane & 3);
            a[0] = xs[ar * XS_STRIDE + ac];
            a[1] = xs[(ar + 8) * XS_STRIDE + ac];
            a[2] = xs[ar * XS_STRIDE + ac + 4];
            a[3] = xs[(ar + 8) * XS_STRIDE + ac + 4];
#pragma unroll
            for (int nt = 0; nt < 8; nt++) {
                unsigned b[2];
                int bn = nt * 8 + (lane >> 2);
                int bk = kk + (lane & 3);
                b[0] = ws[bk * WS_STRIDE + bn];
                b[1] = ws[(bk + 4) * WS_STRIDE + bn];
                mma_tf32(acc[nt], a, b);
            }
        }
        __syncthreads();
    }

    int r0 = rowBase + warp * 16 + (lane >> 2);
    __half* supa = g_support + (size_t)axis * N_NODES * DIM_OUT;
#pragma unroll
    for (int nt = 0; nt < 8; nt++) {
        int col = nt * 8 + 2 * (lane & 3);
        if (r0 < N_NODES)
            *(__half2*)(supa + (size_t)r0 * DIM_OUT + col) =
                __floats2half2_rn(acc[nt][0], acc[nt][1]);
        if (r0 + 8 < N_NODES)
            *(__half2*)(supa + (size_t)(r0 + 8) * DIM_OUT + col) =
                __floats2half2_rn(acc[nt][2], acc[nt][3]);
    }
}

// ---------------- Bucketize: single combined list per row -------------------
__global__ void zero_cnt_kernel() {
    int i = blockIdx.x * blockDim.x + threadIdx.x;
    if (i < N_NODES) g_cnt[i] = 0;
}

// Axis folded into the stored column: c' = ax*N_NODES + c.
// 4 edges per thread with int4/float4 loads -> MLP 4 on atomic/store chains.
__global__ __launch_bounds__(256) void scatter_kernel(
    const int* __restrict__ r0, const int* __restrict__ c0, const float* __restrict__ v0,
    const int* __restrict__ r1, const int* __restrict__ c1, const float* __restrict__ v1,
    const int* __restrict__ r2, const int* __restrict__ c2, const float* __restrict__ v2) {
    int e = (blockIdx.x * 256 + threadIdx.x) * 4;
    if (e >= N_EDGES) return;
    int ax = blockIdx.y;
    const int* row = ax == 0 ? r0 : (ax == 1 ? r1 : r2);
    const int* col = ax == 0 ? c0 : (ax == 1 ? c1 : c2);
    const float* val = ax == 0 ? v0 : (ax == 1 ? v1 : v2);
    int axBase = ax * N_NODES;

    int4 rr = __ldg((const int4*)(row + e));
    int4 cc = __ldg((const int4*)(col + e));
    float4 vv = __ldg((const float4*)(val + e));

    int pa = atomicAdd(&g_cnt[rr.x], 1);
    int pb = atomicAdd(&g_cnt[rr.y], 1);
    int pc = atomicAdd(&g_cnt[rr.z], 1);
    int pd = atomicAdd(&g_cnt[rr.w], 1);
    if (pa < PAD)
        g_bucket[(size_t)rr.x * PAD + pa] =
            ((long long)__float_as_int(vv.x) << 32) | (unsigned)(axBase + cc.x);
    if (pb < PAD)
        g_bucket[(size_t)rr.y * PAD + pb] =
            ((long long)__float_as_int(vv.y) << 32) | (unsigned)(axBase + cc.y);
    if (pc < PAD)
        g_bucket[(size_t)rr.z * PAD + pc] =
            ((long long)__float_as_int(vv.z) << 32) | (unsigned)(axBase + cc.z);
    if (pd < PAD)
        g_bucket[(size_t)rr.w * PAD + pd] =
            ((long long)__float_as_int(vv.w) << 32) | (unsigned)(axBase + cc.w);
}

// ---------------- Pad: zero bucket slots [deg, roundup8(deg)) ---------------
__global__ void pad_kernel() {
    int i = blockIdx.x * blockDim.x + threadIdx.x;     // N_NODES*8 threads
    int r = i >> 3;
    if (r >= N_NODES) return;
    int deg = g_cnt[r];
    if (deg > PAD) deg = PAD;
    int s = deg + (i & 7);
    int padded = (deg + 7) & ~7;
    if (s < padded) g_bucket[(size_t)r * PAD + s] = 0LL;
}

// ---------------- Fused SpMM: 2 warps per row (edge-split) ------------------
// Block = 256 threads = 8 warps = 4 rows. Warp pair (half=0/1) splits the
// row's 8-edge groups by parity; partial sums combined via smem.
// Lane owns cols 2*lane, 2*lane+1 (one half2).
__global__ __launch_bounds__(256) void spmm_fused_kernel(const float* __restrict__ bias,
                                                         float* __restrict__ out) {
    __shared__ float red[4][DIM_OUT];       // 1 KB: partial sums from half=1 warps
    int tid = threadIdx.x;
    int warp = tid >> 5, lane = tid & 31;
    int rowLocal = warp >> 1;               // 0..3
    int half = warp & 1;                    // edge-group parity
    int row = blockIdx.x * 4 + rowLocal;    // N_NODES % 4 == 0 -> always valid

    float a0 = 0.f, a1 = 0.f, b0 = 0.f, b1 = 0.f;   // dual chains
    const __half2* supLane = (const __half2*)g_support + lane;

    int deg = g_cnt[row];
    if (deg > PAD) deg = PAD;
    int ng = (deg + 7) >> 3;
    const uint4* bk = (const uint4*)(g_bucket + (size_t)row * PAD) + half * 4;

#pragma unroll 1
    for (int g = half; g < ng; g += 2, bk += 8) {
        uint4 p0 = __ldg(bk);
        uint4 p1 = __ldg(bk + 1);
        uint4 p2 = __ldg(bk + 2);
        uint4 p3 = __ldg(bk + 3);
        __half2 h0 = __ldg(supLane + (size_t)p0.x * 32);
        __half2 h1 = __ldg(supLane + (size_t)p0.z * 32);
        __half2 h2 = __ldg(supLane + (size_t)p1.x * 32);
        __half2 h3 = __ldg(supLane + (size_t)p1.z * 32);
        __half2 h4 = __ldg(supLane + (size_t)p2.x * 32);
        __half2 h5 = __ldg(supLane + (size_t)p2.z * 32);
        __half2 h6 = __ldg(supLane + (size_t)p3.x * 32);
        __half2 h7 = __ldg(supLane + (size_t)p3.z * 32);
        float2 s;
        float v;
        v = __int_as_float((int)p0.y); s = __half22float2(h0); a0 += v * s.x; a1 += v * s.y;
        v = __int_as_float((int)p0.w); s = __half22float2(h1); a0 += v * s.x; a1 += v * s.y;
        v = __int_as_float((int)p1.y); s = __half22float2(h2); a0 += v * s.x; a1 += v * s.y;
        v = __int_as_float((int)p1.w); s = __half22float2(h3); a0 += v * s.x; a1 += v * s.y;
        v = __int_as_float((int)p2.y); s = __half22float2(h4); b0 += v * s.x; b1 += v * s.y;
        v = __int_as_float((int)p2.w); s = __half22float2(h5); b0 += v * s.x; b1 += v * s.y;
        v = __int_as_float((int)p3.y); s = __half22float2(h6); b0 += v * s.x; b1 += v * s.y;
        v = __int_as_float((int)p3.w); s = __half22float2(h7); b0 += v * s.x; b1 += v * s.y;
    }

    if (half == 1) {
        red[rowLocal][2 * lane] = a0 + b0;
        red[rowLocal][2 * lane + 1] = a1 + b1;
    }
    __syncthreads();
    if (half == 0) {
        int jc = 2 * lane;
        float c0 = __ldg(bias + jc) + __ldg(bias + DIM_OUT + jc) + __ldg(bias + 2 * DIM_OUT + jc);
        float c1 = __ldg(bias + jc + 1) + __ldg(bias + DIM_OUT + jc + 1) + __ldg(bias + 2 * DIM_OUT + jc + 1);
        float r0v = (a0 + b0) + red[rowLocal][jc];
        float r1v = (a1 + b1) + red[rowLocal][jc + 1];
        ((float2*)(out + (size_t)row * DIM_OUT))[lane] = make_float2(r0v + c0, r1v + c1);
    }
}

// ---------------- Stream/event resources (static init, pre-checkpoint) ------
struct StreamRes {
    cudaStream_t s2 = nullptr;
    cudaEvent_t evFork = nullptr, evJoin = nullptr;
    bool ok = false;
    StreamRes() {
        ok = (cudaStreamCreateWithFlags(&s2, cudaStreamNonBlocking) == cudaSuccess) &&
             (cudaEventCreateWithFlags(&evFork, cudaEventDisableTiming) == cudaSuccess) &&
             (cudaEventCreateWithFlags(&evJoin, cudaEventDisableTiming) == cudaSuccess);
    }
};
static StreamRes g_sr;

extern "C" void kernel_launch(void* const* d_in, const int* in_sizes, int n_in,
                              void* d_out, int out_size) {
    const float *x = nullptr, *w = nullptr, *b = nullptr;
    const void* eptr[9];
    int ne = 0;
    for (int i = 0; i < n_in; i++) {
        long s = in_sizes[i];
        if (s == (long)N_NODES * DIM_IN) x = (const float*)d_in[i];
        else if (s == 3 * DIM_IN * DIM_OUT) w = (const float*)d_in[i];
        else if (s == 3 * DIM_OUT) b = (const float*)d_in[i];
        else if (s == N_EDGES && ne < 9) eptr[ne++] = d_in[i];
    }
    float* out = (float*)d_out;

    if (g_sr.ok) {
        // Fork: gemm on s2; bucket pipeline on the capture stream.
        cudaEventRecord(g_sr.evFork, 0);
        cudaStreamWaitEvent(g_sr.s2, g_sr.evFork, 0);
        gemm_tf32_kernel<<<dim3((N_NODES + 127) / 128, 3), 256, 0, g_sr.s2>>>(x, w);
        cudaEventRecord(g_sr.evJoin, g_sr.s2);

        zero_cnt_kernel<<<(N_NODES + 1023) / 1024, 1024>>>();
        scatter_kernel<<<dim3((N_EDGES / 4 + 255) / 256, 3), 256>>>(
            (const int*)eptr[0], (const int*)eptr[1], (const float*)eptr[2],
            (const int*)eptr[3], (const int*)eptr[4], (const float*)eptr[5],
            (const int*)eptr[6], (const int*)eptr[7], (const float*)eptr[8]);
        pad_kernel<<<(N_NODES * 8 + 255) / 256, 256>>>();

        cudaStreamWaitEvent(0, g_sr.evJoin, 0);   // join before spmm
    } else {
        zero_cnt_kernel<<<(N_NODES + 1023) / 1024, 1024>>>();
        scatter_kernel<<<dim3((N_EDGES / 4 + 255) / 256, 3), 256>>>(
            (const int*)eptr[0], (const int*)eptr[1], (const float*)eptr[2],
            (const int*)eptr[3], (const int*)eptr[4], (const float*)eptr[5],
            (const int*)eptr[6], (const int*)eptr[7], (const float*)eptr[8]);
        pad_kernel<<<(N_NODES * 8 + 255) / 256, 256>>>();
        gemm_tf32_kernel<<<dim3((N_NODES + 127) / 128, 3), 256>>>(x, w);
    }

    spmm_fused_kernel<<<N_NODES / 4, 256>>>(b, out);
}